// round 6
// baseline (speedup 1.0000x reference)
#include <cuda_runtime.h>
#include <math.h>

#define BB 8
#define LL 2048
#define DD 1024
#define ZZ 128
#define HH 2048
#define NE 16
#define GG 32
#define MG 32
#define NOUT 4224
#define MAXPOSC 2048
#define EPSF 1e-5f
#define PRIORC 2.0f
#define EC 16
#define ECL (LL/EC)
#define TCH 256         // tn chunk length
#define TNC (LL/TCH)    // 8 chunks

// ---------------- scratch ----------------
__device__ float g_xn[(size_t)BB*LL*DD];
__device__ float g_v[(size_t)BB*LL*HH];
__device__ float g_mx[(size_t)BB*LL*DD];
__device__ float g_base[(size_t)BB*LL*NOUT];
__device__ float g_q[(size_t)BB*LL*ZZ];
__device__ float g_k[(size_t)BB*LL*ZZ];
__device__ float g_S[(size_t)BB*LL*LL];
__device__ float g_hatt[(size_t)BB*LL*HH];
__device__ float g_Wv[(size_t)HH*DD];
__device__ float g_Wmx[(size_t)NOUT*DD];
__device__ float g_Wh[(size_t)DD*HH];
__device__ float g_ts1[(size_t)BB*GG*LL];
__device__ float g_ts2[(size_t)BB*GG*LL];
__device__ float g_ct[(size_t)BB*GG*TNC*2];
__device__ float g_off[(size_t)BB*GG*TNC*2];

__device__ __forceinline__ float sigmoidf_(float v) { return 1.f/(1.f+__expf(-v)); }
__device__ __forceinline__ float siluf_(float v)    { return v/(1.f+__expf(-v)); }
__device__ __forceinline__ unsigned f2tf(float f) {
    unsigned u; asm("cvt.rna.tf32.f32 %0, %1;" : "=r"(u) : "f"(f)); return u;
}
__device__ __forceinline__ float tfr(float f) { return __uint_as_float(f2tf(f)); }
__device__ __forceinline__ void cpa16(unsigned d, const void* g) {
    asm volatile("cp.async.cg.shared.global [%0], [%1], 16;" :: "r"(d), "l"(g));
}
__device__ __forceinline__ void cpcommit() { asm volatile("cp.async.commit_group;"); }
template<int N> __device__ __forceinline__ void cpwait() {
    asm volatile("cp.async.wait_group %0;" :: "n"(N));
}

// ---------------- tf32 rounding copy ----------------
__global__ void round_kernel(const float* __restrict__ src, float* __restrict__ dst, int n4) {
    int i = blockIdx.x*blockDim.x + threadIdx.x;
    if (i >= n4) return;
    float4 v = ((const float4*)src)[i];
    v.x = tfr(v.x); v.y = tfr(v.y); v.z = tfr(v.z); v.w = tfr(v.w);
    ((float4*)dst)[i] = v;
}

// ---------------- TN phase 1: per-(bg, chunk) group sums ----------------
// grid = BB*GG*TNC = 2048, block 256. 8 threads per t, float4 each (32 ch).
__global__ void tn1_kernel(const float* __restrict__ x,
                           float* __restrict__ ts1, float* __restrict__ ts2,
                           float* __restrict__ ct) {
    int blk = blockIdx.x;
    int ch_ = blk & (TNC-1);
    int bg  = blk >> 3;
    int b = bg / GG, g = bg % GG;
    int tid = threadIdx.x;
    int lane8 = tid & 7;
    int trow = tid >> 3;            // 0..31
    __shared__ float sh1[TCH], sh2[TCH];

    const float* xp = x + (size_t)b*LL*DD + g*MG + lane8*4;
    int t0 = ch_*TCH;
    #pragma unroll
    for (int w = 0; w < TCH/32; w++) {
        int t = w*32 + trow;
        float4 v = *(const float4*)(xp + (size_t)(t0 + t)*DD);
        float s = v.x + v.y + v.z + v.w;
        float s2 = v.x*v.x + v.y*v.y + v.z*v.z + v.w*v.w;
        #pragma unroll
        for (int o = 4; o; o >>= 1) {
            s  += __shfl_xor_sync(0xffffffffu, s,  o);
            s2 += __shfl_xor_sync(0xffffffffu, s2, o);
        }
        if (lane8 == 0) { sh1[t] = s; sh2[t] = s2; }
    }
    __syncthreads();
    // write per-t sums and block totals
    float* o1 = ts1 + (size_t)bg*LL + t0;
    float* o2 = ts2 + (size_t)bg*LL + t0;
    if (tid < TCH) { o1[tid] = sh1[tid]; o2[tid] = sh2[tid]; }
    // reduce totals
    __syncthreads();
    if (tid < 128) { sh1[tid] += sh1[tid+128]; sh2[tid] += sh2[tid+128]; }
    __syncthreads();
    if (tid < 64) { sh1[tid] += sh1[tid+64]; sh2[tid] += sh2[tid+64]; }
    __syncthreads();
    if (tid < 32) {
        float a = sh1[tid] + sh1[tid+32];
        float c = sh2[tid] + sh2[tid+32];
        #pragma unroll
        for (int o = 16; o; o >>= 1) {
            a += __shfl_xor_sync(0xffffffffu, a, o);
            c += __shfl_xor_sync(0xffffffffu, c, o);
        }
        if (tid == 0) {
            ct[((size_t)bg*TNC + ch_)*2]     = a;
            ct[((size_t)bg*TNC + ch_)*2 + 1] = c;
        }
    }
}

// ---------------- TN phase 2: exclusive scan of chunk totals ----------------
__global__ void tn2_kernel(const float* __restrict__ ct, float* __restrict__ off) {
    int bg = blockIdx.x*blockDim.x + threadIdx.x;
    if (bg >= BB*GG) return;
    float p1 = 0.f, p2 = 0.f;
    #pragma unroll
    for (int c = 0; c < TNC; c++) {
        off[((size_t)bg*TNC + c)*2]     = p1;
        off[((size_t)bg*TNC + c)*2 + 1] = p2;
        p1 += ct[((size_t)bg*TNC + c)*2];
        p2 += ct[((size_t)bg*TNC + c)*2 + 1];
    }
}

// ---------------- TN phase 3: in-chunk scan + normalize ----------------
__global__ void tn3_kernel(const float* __restrict__ x,
                           const float* __restrict__ ts1, const float* __restrict__ ts2,
                           const float* __restrict__ off,
                           const float* __restrict__ pm_, const float* __restrict__ plv_,
                           const float* __restrict__ w, const float* __restrict__ bias,
                           float* __restrict__ xn) {
    int blk = blockIdx.x;
    int ch_ = blk & (TNC-1);
    int bg  = blk >> 3;
    int b = bg / GG, g = bg % GG;
    int tid = threadIdx.x;
    __shared__ float c1[TCH], c2[TCH];
    __shared__ float wsum[16];

    int t0 = ch_*TCH;
    // inclusive scan of 256 values (warp scan + warp offsets)
    {
        float a = ts1[(size_t)bg*LL + t0 + tid];
        float c = ts2[(size_t)bg*LL + t0 + tid];
        int lane = tid & 31, wp = tid >> 5;
        #pragma unroll
        for (int o = 1; o < 32; o <<= 1) {
            float ta = __shfl_up_sync(0xffffffffu, a, o);
            float tc = __shfl_up_sync(0xffffffffu, c, o);
            if (lane >= o) { a += ta; c += tc; }
        }
        if (lane == 31) { wsum[wp] = a; wsum[8 + wp] = c; }
        __syncthreads();
        if (wp == 0 && lane < 8) {
            float v1 = wsum[lane], v2 = wsum[8 + lane];
            #pragma unroll
            for (int o = 1; o < 8; o <<= 1) {
                float t1 = __shfl_up_sync(0xffu, v1, o);
                float t2 = __shfl_up_sync(0xffu, v2, o);
                if (lane >= o) { v1 += t1; v2 += t2; }
            }
            wsum[lane] = v1; wsum[8 + lane] = v2;
        }
        __syncthreads();
        float o1 = off[((size_t)bg*TNC + ch_)*2];
        float o2 = off[((size_t)bg*TNC + ch_)*2 + 1];
        if (wp > 0) { o1 += wsum[wp - 1]; o2 += wsum[8 + wp - 1]; }
        c1[tid] = a + o1;
        c2[tid] = c + o2;
    }
    __syncthreads();

    float pm = pm_[g];
    float pv = expf(plv_[g]);
    int lane8 = tid & 7;
    int trow = tid >> 3;
    float4 wg4 = *(const float4*)(w + g*MG + lane8*4);
    float4 bs4 = *(const float4*)(bias + g*MG + lane8*4);
    const float* xp = x + (size_t)b*LL*DD + g*MG + lane8*4;
    float* op = xn + (size_t)b*LL*DD + g*MG + lane8*4;
    #pragma unroll
    for (int wv = 0; wv < TCH/32; wv++) {
        int t = wv*32 + trow;
        int tg = t0 + t;
        float cnt  = PRIORC + (float)MG * (float)(tg + 1);
        float mean = (PRIORC*pm + c1[t]) / cnt;
        float var  = (PRIORC*(pv + pm*pm) + c2[t]) / cnt - mean*mean;
        float inv  = rsqrtf(var + EPSF);
        float4 v = *(const float4*)(xp + (size_t)tg*DD);
        float4 o;
        o.x = tfr((v.x - mean)*inv*wg4.x + bs4.x);
        o.y = tfr((v.y - mean)*inv*wg4.y + bs4.y);
        o.z = tfr((v.z - mean)*inv*wg4.z + bs4.z);
        o.w = tfr((v.w - mean)*inv*wg4.w + bs4.w);
        *(float4*)(op + (size_t)tg*DD) = o;
    }
}

// ---------------- MultiHeadEMA: chunked parallel scan ----------------
__global__ void ema2_kernel(const float* __restrict__ xn,
                            const float* __restrict__ delta, const float* __restrict__ alpha,
                            const float* __restrict__ ebeta, const float* __restrict__ egamma,
                            const float* __restrict__ omega, float* __restrict__ out) {
    __shared__ float fin[EC][16][NE];
    __shared__ float ini[EC][16][NE];
    int blk = blockIdx.x;
    int b = blk >> 6;
    int d0 = (blk & 63) << 4;
    int tid = threadIdx.x;
    int ch = tid & 15, ck = tid >> 4;
    int d = d0 + ch;

    float q[NE], c[NE], s[NE];
    const float scale = 0.25f;
    #pragma unroll
    for (int n = 0; n < NE; n++) {
        float p = 1.f/(1.f+expf(-delta[d*NE+n]));
        float a = 1.f/(1.f+expf(-alpha[d*NE+n]));
        q[n] = 1.f - p*a;
        c[n] = p * ebeta[d*NE+n] * egamma[d*NE+n] * scale;
        s[n] = 0.f;
    }
    const float* xp = xn + ((size_t)b*LL + (size_t)ck*ECL)*DD + d;

    for (int t = 0; t < ECL; t++) {
        float xv = xp[(size_t)t*DD];
        #pragma unroll
        for (int n = 0; n < NE; n++) s[n] = q[n]*s[n] + xv;
    }
    #pragma unroll
    for (int n = 0; n < NE; n++) fin[ck][ch][n] = s[n];
    __syncthreads();

    {
        int ch2 = tid >> 4, n2 = tid & 15;
        int d2 = d0 + ch2;
        float p2 = 1.f/(1.f+expf(-delta[d2*NE+n2]));
        float a2 = 1.f/(1.f+expf(-alpha[d2*NE+n2]));
        float qq = 1.f - p2*a2;
        float q128 = __powf(qq, (float)ECL);
        float st = 0.f;
        #pragma unroll
        for (int k2 = 0; k2 < EC; k2++) {
            ini[k2][ch2][n2] = st;
            st = q128*st + fin[k2][ch2][n2];
        }
    }
    __syncthreads();

    #pragma unroll
    for (int n = 0; n < NE; n++) s[n] = ini[ck][ch][n];
    float om = omega[d];
    float* op = out + ((size_t)b*LL + (size_t)ck*ECL)*DD + d;
    for (int t = 0; t < ECL; t++) {
        float xv = xp[(size_t)t*DD];
        float acc = 0.f;
        #pragma unroll
        for (int n = 0; n < NE; n++) { s[n] = q[n]*s[n] + xv; acc += c[n]*s[n]; }
        op[(size_t)t*DD] = acc + om*xv;
    }
}

// ---------------- RMS norm ----------------
__global__ void rms_kernel(float* __restrict__ mx, const float* __restrict__ w) {
    int row = blockIdx.x;
    int tid = threadIdx.x;
    float* p = mx + (size_t)row*DD;
    float v[4];
    float ss = 0.f;
    #pragma unroll
    for (int i = 0; i < 4; i++) { v[i] = p[tid + 256*i]; ss += v[i]*v[i]; }
    __shared__ float red[256];
    red[tid] = ss; __syncthreads();
    #pragma unroll
    for (int o = 128; o; o >>= 1) { if (tid < o) red[tid] += red[tid+o]; __syncthreads(); }
    float inv = rsqrtf(red[0]/(float)DD + EPSF);
    #pragma unroll
    for (int i = 0; i < 4; i++) { int dc = tid + 256*i; p[dc] = tfr(v[i]*inv*w[dc]); }
}

// ============ tf32 GEMM, cp.async 3-stage pipeline ============
template<int TRANSB, int CAUSAL, int KLIM>
__global__ void __launch_bounds__(256, 2)
mma_gemm(const float* __restrict__ A, const float* __restrict__ B,
         const float* __restrict__ bias, float* __restrict__ C,
         int M, int Nn, int K,
         long long sA, long long sB, long long sC, int act,
         const float* __restrict__ aux, const float* __restrict__ xres) {
    int rowBase = blockIdx.y * 128, colBase = blockIdx.x * 128;
    if (CAUSAL && colBase > rowBase) return;
    A += (long long)blockIdx.z * sA;
    B += (long long)blockIdx.z * sB;
    C += (long long)blockIdx.z * sC;

    extern __shared__ unsigned sm[];
    unsigned sbase = (unsigned)__cvta_generic_to_shared(sm);

    const int tid = threadIdx.x;
    const int lane = tid & 31, wid = tid >> 5;
    const int wm = (wid >> 2) * 64, wn = (wid & 3) * 32;
    const int g = lane >> 2, t = lane & 3;

    const int Kend = KLIM ? (rowBase + 128) : K;
    const int NIT = Kend >> 5;

    unsigned aoff[4], boff[4];
    const float* agp[4];
    const float* bgp[4];
    long long bstep;
    #pragma unroll
    for (int i = 0; i < 4; i++) {
        int idx = tid + 256*i;
        int r = idx >> 3, k4 = (idx & 7) << 2;
        aoff[i] = (unsigned)((r*32 + (k4 ^ ((r & 7) << 2))) * 4);
        agp[i]  = A + (long long)(rowBase + r)*K + k4;
        if (TRANSB) {
            boff[i] = aoff[i];
            bgp[i]  = B + (long long)(colBase + r)*K + k4;
        } else {
            int kk = idx >> 5, n4 = (idx & 31) << 2;
            boff[i] = (unsigned)((kk*128 + (n4 ^ ((kk & 3) << 3))) * 4);
            bgp[i]  = B + (long long)kk*Nn + colBase + n4;
        }
    }
    bstep = TRANSB ? 32ll : 32ll*Nn;

    auto issue = [&](int it, int st) {
        unsigned stg = sbase + (unsigned)(st * 32768);
        long long ka = (long long)it * 32;
        #pragma unroll
        for (int i = 0; i < 4; i++) cpa16(stg + aoff[i], agp[i] + ka);
        long long kb = (long long)it * bstep;
        #pragma unroll
        for (int i = 0; i < 4; i++) cpa16(stg + 16384u + boff[i], bgp[i] + kb);
        cpcommit();
    };

    float acc[4][4][4];
    #pragma unroll
    for (int mi = 0; mi < 4; mi++)
        #pragma unroll
        for (int ni = 0; ni < 4; ni++)
            #pragma unroll
            for (int e = 0; e < 4; e++) acc[mi][ni][e] = 0.f;

    issue(0, 0);
    if (NIT > 1) issue(1, 1);

    int st = 0, stn = 2;   // stn = stage for it+2
    for (int it = 0; it < NIT; it++) {
        if (it + 1 < NIT) cpwait<1>(); else cpwait<0>();
        __syncthreads();
        if (it + 2 < NIT) {
            issue(it + 2, stn);
        }

        const unsigned* Ab = sm + st * 8192;
        const unsigned* Bb = Ab + 4096;

        #pragma unroll
        for (int ks = 0; ks < 4; ks++) {
            unsigned af[4][4], bf[4][2];
            #pragma unroll
            for (int mi = 0; mi < 4; mi++) {
                int r0 = wm + mi*16 + g;
                int sw = (r0 & 7) << 2;
                int c0 = ks*8 + t;
                af[mi][0] = Ab[r0*32 + (c0 ^ sw)];
                af[mi][1] = Ab[(r0 + 8)*32 + (c0 ^ (((r0+8) & 7) << 2))];
                af[mi][2] = Ab[r0*32 + ((c0 + 4) ^ sw)];
                af[mi][3] = Ab[(r0 + 8)*32 + ((c0 + 4) ^ (((r0+8) & 7) << 2))];
            }
            #pragma unroll
            for (int ni = 0; ni < 4; ni++) {
                int n0 = wn + ni*8 + g;
                int k0 = ks*8 + t;
                if (TRANSB) {
                    int sw = (n0 & 7) << 2;
                    bf[ni][0] = Bb[n0*32 + (k0 ^ sw)];
                    bf[ni][1] = Bb[n0*32 + ((k0 + 4) ^ sw)];
                } else {
                    int sw0 = (k0 & 3) << 3;
                    int sw1 = ((k0 + 4) & 3) << 3;
                    bf[ni][0] = Bb[k0*128 + (n0 ^ sw0)];
                    bf[ni][1] = Bb[(k0 + 4)*128 + (n0 ^ sw1)];
                }
            }
            #pragma unroll
            for (int mi = 0; mi < 4; mi++)
                #pragma unroll
                for (int ni = 0; ni < 4; ni++) {
                    asm volatile(
                        "mma.sync.aligned.m16n8k8.row.col.f32.tf32.tf32.f32 "
                        "{%0,%1,%2,%3},{%4,%5,%6,%7},{%8,%9},{%0,%1,%2,%3};"
                        : "+f"(acc[mi][ni][0]), "+f"(acc[mi][ni][1]),
                          "+f"(acc[mi][ni][2]), "+f"(acc[mi][ni][3])
                        : "r"(af[mi][0]), "r"(af[mi][1]), "r"(af[mi][2]), "r"(af[mi][3]),
                          "r"(bf[ni][0]), "r"(bf[ni][1]));
                }
        }
        __syncthreads();
        st  = (st  == 2) ? 0 : st + 1;
        stn = (stn == 2) ? 0 : stn + 1;
    }

    const float* auxb = aux ? aux + (long long)blockIdx.z * LL * NOUT : aux;
    #pragma unroll
    for (int mi = 0; mi < 4; mi++) {
        #pragma unroll
        for (int ni = 0; ni < 4; ni++) {
            int c = colBase + wn + ni*8 + 2*t;
            float b0 = 0.f, b1 = 0.f;
            if (bias) { b0 = bias[c]; b1 = bias[c+1]; }
            #pragma unroll
            for (int h = 0; h < 2; h++) {
                long long r = rowBase + wm + mi*16 + g + 8*h;
                float v0 = acc[mi][ni][2*h]   + b0;
                float v1 = acc[mi][ni][2*h+1] + b1;
                if (act == 1) { v0 = tfr(siluf_(v0)); v1 = tfr(siluf_(v1)); }
                else if (act == 3) {
                    v0 = tfr(v0 * siluf_(auxb[r*NOUT + c]));
                    v1 = tfr(v1 * siluf_(auxb[r*NOUT + c + 1]));
                } else if (act == 4) {
                    float u0  = sigmoidf_(auxb[r*NOUT + c]);
                    float u1  = sigmoidf_(auxb[r*NOUT + c + 1]);
                    float hx0 = auxb[r*NOUT + (DD+ZZ+HH) + c];
                    float hx1 = auxb[r*NOUT + (DD+ZZ+HH) + c + 1];
                    float x0  = xres[r*Nn + c];
                    float x1  = xres[r*Nn + c + 1];
                    v0 = x0 + u0*(siluf_(hx0 + v0) - x0);
                    v1 = x1 + u1*(siluf_(hx1 + v1) - x1);
                }
                *(float2*)&C[r*Nn + c] = make_float2(v0, v1);
            }
        }
    }
}

// ---------------- q/k projection ----------------
__global__ void prepqk_kernel(const float* __restrict__ base,
                              const float* __restrict__ qg, const float* __restrict__ qb,
                              float* __restrict__ q, float* __restrict__ k) {
    int gid = blockIdx.x*blockDim.x + threadIdx.x;
    if (gid >= BB*LL*ZZ) return;
    int zi  = gid & (ZZ-1);
    int row = gid >> 7;
    float v = base[(size_t)row*NOUT + DD + zi];
    v = siluf_(v);
    q[gid] = tfr((v*qg[zi]    + qb[zi]) * 0.08838834764831845f);
    k[gid] = tfr( v*qg[ZZ+zi] + qb[ZZ+zi]);
}

// ---------------- softmax ----------------
__global__ void softmax_kernel(float* __restrict__ S, const float* __restrict__ rel) {
    int i = blockIdx.x, b = blockIdx.y;
    int tid = threadIdx.x;
    float* row = S + ((size_t)b*LL + i)*LL;
    __shared__ float sh[LL];
    __shared__ float red[256];
    int len = i + 1;
    const float* rb = rel + (MAXPOSC - 1) - i;
    float mx = -1e30f;
    for (int j = tid; j < len; j += 256) {
        float v = row[j] + rb[j];
        sh[j] = v; mx = fmaxf(mx, v);
    }
    red[tid] = mx; __syncthreads();
    #pragma unroll
    for (int o = 128; o; o >>= 1) { if (tid < o) red[tid] = fmaxf(red[tid], red[tid+o]); __syncthreads(); }
    mx = red[0]; __syncthreads();
    float sum = 0.f;
    for (int j = tid; j < len; j += 256) { float e = __expf(sh[j]-mx); sh[j] = e; sum += e; }
    red[tid] = sum; __syncthreads();
    #pragma unroll
    for (int o = 128; o; o >>= 1) { if (tid < o) red[tid] += red[tid+o]; __syncthreads(); }
    float inv = 1.f / red[0];
    for (int j = tid; j < len; j += 256) row[j] = tfr(sh[j]*inv);
    int zend = ((i >> 7) + 1) << 7;
    for (int j = len + tid; j < zend; j += 256) row[j] = 0.f;
}

// ---------------- host launch ----------------
extern "C" void kernel_launch(void* const* d_in, const int* in_sizes, int n_in,
                              void* d_out, int out_size) {
    const float* x      = (const float*)d_in[0];
    const float* pm     = (const float*)d_in[1];
    const float* plv    = (const float*)d_in[2];
    const float* tnw    = (const float*)d_in[3];
    const float* tnb    = (const float*)d_in[4];
    const float* delta  = (const float*)d_in[5];
    const float* alpha  = (const float*)d_in[6];
    const float* ebeta  = (const float*)d_in[7];
    const float* egamma = (const float*)d_in[8];
    const float* omega  = (const float*)d_in[9];
    const float* rmsw   = (const float*)d_in[10];
    const float* Wv     = (const float*)d_in[11];
    const float* bv     = (const float*)d_in[12];
    const float* Wmx    = (const float*)d_in[13];
    const float* bmx    = (const float*)d_in[14];
    const float* Wh     = (const float*)d_in[15];
    const float* qg     = (const float*)d_in[16];
    const float* qb     = (const float*)d_in[17];
    const float* rel    = (const float*)d_in[18];

    float *xn, *v, *mx, *base, *q, *k, *S, *hatt, *wv, *wmx, *wh;
    float *ts1, *ts2, *ct, *off;
    cudaGetSymbolAddress((void**)&xn,   g_xn);
    cudaGetSymbolAddress((void**)&v,    g_v);
    cudaGetSymbolAddress((void**)&mx,   g_mx);
    cudaGetSymbolAddress((void**)&base, g_base);
    cudaGetSymbolAddress((void**)&q,    g_q);
    cudaGetSymbolAddress((void**)&k,    g_k);
    cudaGetSymbolAddress((void**)&S,    g_S);
    cudaGetSymbolAddress((void**)&hatt, g_hatt);
    cudaGetSymbolAddress((void**)&wv,   g_Wv);
    cudaGetSymbolAddress((void**)&wmx,  g_Wmx);
    cudaGetSymbolAddress((void**)&wh,   g_Wh);
    cudaGetSymbolAddress((void**)&ts1,  g_ts1);
    cudaGetSymbolAddress((void**)&ts2,  g_ts2);
    cudaGetSymbolAddress((void**)&ct,   g_ct);
    cudaGetSymbolAddress((void**)&off,  g_off);

    cudaFuncSetAttribute(mma_gemm<1,0,0>, cudaFuncAttributeMaxDynamicSharedMemorySize, 98304);
    cudaFuncSetAttribute(mma_gemm<1,1,0>, cudaFuncAttributeMaxDynamicSharedMemorySize, 98304);
    cudaFuncSetAttribute(mma_gemm<0,0,1>, cudaFuncAttributeMaxDynamicSharedMemorySize, 98304);

    const int Mrows = BB*LL;

    // 0) tf32-round weights
    round_kernel<<<(HH*DD/4 + 255)/256, 256>>>(Wv,  wv,  HH*DD/4);
    round_kernel<<<(NOUT*DD/4 + 255)/256, 256>>>(Wmx, wmx, NOUT*DD/4);
    round_kernel<<<(DD*HH/4 + 255)/256, 256>>>(Wh,  wh,  DD*HH/4);

    // 1) timestep norm, chunked
    tn1_kernel<<<BB*GG*TNC, 256>>>(x, ts1, ts2, ct);
    tn2_kernel<<<1, 256>>>(ct, off);
    tn3_kernel<<<BB*GG*TNC, 256>>>(x, ts1, ts2, off, pm, plv, tnw, tnb, xn);

    // 2) v = tf32(silu(xn @ Wv^T + bv))
    mma_gemm<1,0,0><<<dim3(HH/128, Mrows/128, 1), 256, 98304>>>(
        xn, wv, bv, v, Mrows, HH, DD, 0, 0, 0, 1, nullptr, nullptr);

    // 3) EMA
    ema2_kernel<<<(BB*DD)/16, 256>>>(xn, delta, alpha, ebeta, egamma, omega, mx);

    // 4) RMS norm
    rms_kernel<<<Mrows, 256>>>(mx, rmsw);

    // 5) base = mx @ Wmx^T + bmx
    mma_gemm<1,0,0><<<dim3(NOUT/128, Mrows/128, 1), 256, 98304>>>(
        mx, wmx, bmx, base, Mrows, NOUT, DD, 0, 0, 0, 0, nullptr, nullptr);

    // 6) q, k
    prepqk_kernel<<<(BB*LL*ZZ)/256, 256>>>(base, qg, qb, q, k);

    // 7) S = q @ k^T
    mma_gemm<1,1,0><<<dim3(LL/128, LL/128, BB), 256, 98304>>>(
        q, k, nullptr, S, LL, LL, ZZ,
        (long long)LL*ZZ, (long long)LL*ZZ, (long long)LL*LL, 0, nullptr, nullptr);

    // 8) softmax
    softmax_kernel<<<dim3(LL, BB), 256>>>(S, rel);

    // 9) h_att = (P @ v) * silu(r)
    mma_gemm<0,0,1><<<dim3(HH/128, LL/128, BB), 256, 98304>>>(
        S, v, nullptr, hatt, LL, HH, LL,
        (long long)LL*LL, (long long)LL*HH, (long long)LL*HH, 3, base + DD + ZZ, nullptr);

    // 10) final gate fused into Wh GEMM
    mma_gemm<1,0,0><<<dim3(DD/128, Mrows/128, 1), 256, 98304>>>(
        hatt, wh, nullptr, (float*)d_out, Mrows, DD, HH, 0, 0, 0, 4, base, x);
}

// round 12
// speedup vs baseline: 2.3247x; 2.3247x over previous
#include <cuda_runtime.h>
#include <cuda_fp16.h>
#include <math.h>

#define BB 8
#define LL 2048
#define DD 1024
#define ZZ 128
#define HH 2048
#define NE 16
#define GG 32
#define MG 32
#define NOUT 4224
#define MAXPOSC 2048
#define EPSF 1e-5f
#define PRIORC 2.0f
#define EC 16
#define ECL (LL/EC)
#define TCH 256
#define TNC (LL/TCH)

// ---------------- scratch ----------------
__device__ __half g_xnh [(size_t)BB*LL*DD];
__device__ __half g_vT  [(size_t)BB*LL*HH];   // [b][h][l]
__device__ float  g_mx  [(size_t)BB*LL*DD];
__device__ __half g_mxh [(size_t)BB*LL*DD];
__device__ float  g_base[(size_t)BB*LL*NOUT];
__device__ __half g_qh  [(size_t)BB*LL*ZZ];
__device__ __half g_kh  [(size_t)BB*LL*ZZ];
__device__ float  g_S   [(size_t)BB*LL*LL];
__device__ __half g_Ph  [(size_t)BB*LL*LL];
__device__ __half g_hatth[(size_t)BB*LL*HH];
__device__ __half g_Wvh [(size_t)HH*DD];
__device__ __half g_Wmxh[(size_t)NOUT*DD];
__device__ __half g_Whh [(size_t)DD*HH];
__device__ float  g_ts1[(size_t)BB*GG*LL];
__device__ float  g_ts2[(size_t)BB*GG*LL];
__device__ float  g_ct [(size_t)BB*GG*TNC*2];
__device__ float  g_off[(size_t)BB*GG*TNC*2];

__device__ __forceinline__ float sigmoidf_(float v) { return 1.f/(1.f+__expf(-v)); }
__device__ __forceinline__ float siluf_(float v)    { return v/(1.f+__expf(-v)); }
__device__ __forceinline__ void cpa16(unsigned d, const void* g) {
    asm volatile("cp.async.cg.shared.global [%0], [%1], 16;" :: "r"(d), "l"(g));
}
__device__ __forceinline__ void cpcommit() { asm volatile("cp.async.commit_group;"); }
template<int N> __device__ __forceinline__ void cpwait() {
    asm volatile("cp.async.wait_group %0;" :: "n"(N));
}
__device__ __forceinline__ unsigned packh2(float a, float b) {
    __half2 h = __floats2half2_rn(a, b);
    return *(unsigned*)&h;
}

// ---------------- fp32 -> fp16 copy ----------------
__global__ void roundh_kernel(const float* __restrict__ src, __half* __restrict__ dst, int n4) {
    int i = blockIdx.x*blockDim.x + threadIdx.x;
    if (i >= n4) return;
    float4 v = ((const float4*)src)[i];
    ((uint2*)dst)[i] = make_uint2(packh2(v.x, v.y), packh2(v.z, v.w));
}

// ---------------- TN phase 1 ----------------
__global__ void tn1_kernel(const float* __restrict__ x,
                           float* __restrict__ ts1, float* __restrict__ ts2,
                           float* __restrict__ ct) {
    int blk = blockIdx.x;
    int ch_ = blk & (TNC-1);
    int bg  = blk >> 3;
    int b = bg / GG, g = bg % GG;
    int tid = threadIdx.x;
    int lane8 = tid & 7;
    int trow = tid >> 3;
    __shared__ float sh1[TCH], sh2[TCH];

    const float* xp = x + (size_t)b*LL*DD + g*MG + lane8*4;
    int t0 = ch_*TCH;
    #pragma unroll
    for (int w = 0; w < TCH/32; w++) {
        int t = w*32 + trow;
        float4 v = *(const float4*)(xp + (size_t)(t0 + t)*DD);
        float s = v.x + v.y + v.z + v.w;
        float s2 = v.x*v.x + v.y*v.y + v.z*v.z + v.w*v.w;
        #pragma unroll
        for (int o = 4; o; o >>= 1) {
            s  += __shfl_xor_sync(0xffffffffu, s,  o);
            s2 += __shfl_xor_sync(0xffffffffu, s2, o);
        }
        if (lane8 == 0) { sh1[t] = s; sh2[t] = s2; }
    }
    __syncthreads();
    float* o1 = ts1 + (size_t)bg*LL + t0;
    float* o2 = ts2 + (size_t)bg*LL + t0;
    if (tid < TCH) { o1[tid] = sh1[tid]; o2[tid] = sh2[tid]; }
    __syncthreads();
    if (tid < 128) { sh1[tid] += sh1[tid+128]; sh2[tid] += sh2[tid+128]; }
    __syncthreads();
    if (tid < 64) { sh1[tid] += sh1[tid+64]; sh2[tid] += sh2[tid+64]; }
    __syncthreads();
    if (tid < 32) {
        float a = sh1[tid] + sh1[tid+32];
        float c = sh2[tid] + sh2[tid+32];
        #pragma unroll
        for (int o = 16; o; o >>= 1) {
            a += __shfl_xor_sync(0xffffffffu, a, o);
            c += __shfl_xor_sync(0xffffffffu, c, o);
        }
        if (tid == 0) {
            ct[((size_t)bg*TNC + ch_)*2]     = a;
            ct[((size_t)bg*TNC + ch_)*2 + 1] = c;
        }
    }
}

// ---------------- TN phase 2 ----------------
__global__ void tn2_kernel(const float* __restrict__ ct, float* __restrict__ off) {
    int bg = blockIdx.x*blockDim.x + threadIdx.x;
    if (bg >= BB*GG) return;
    float p1 = 0.f, p2 = 0.f;
    #pragma unroll
    for (int c = 0; c < TNC; c++) {
        off[((size_t)bg*TNC + c)*2]     = p1;
        off[((size_t)bg*TNC + c)*2 + 1] = p2;
        p1 += ct[((size_t)bg*TNC + c)*2];
        p2 += ct[((size_t)bg*TNC + c)*2 + 1];
    }
}

// ---------------- TN phase 3: scan + normalize -> half ----------------
__global__ void tn3_kernel(const float* __restrict__ x,
                           const float* __restrict__ ts1, const float* __restrict__ ts2,
                           const float* __restrict__ off,
                           const float* __restrict__ pm_, const float* __restrict__ plv_,
                           const float* __restrict__ w, const float* __restrict__ bias,
                           __half* __restrict__ xn) {
    int blk = blockIdx.x;
    int ch_ = blk & (TNC-1);
    int bg  = blk >> 3;
    int b = bg / GG, g = bg % GG;
    int tid = threadIdx.x;
    __shared__ float c1[TCH], c2[TCH];
    __shared__ float wsum[16];

    int t0 = ch_*TCH;
    {
        float a = ts1[(size_t)bg*LL + t0 + tid];
        float c = ts2[(size_t)bg*LL + t0 + tid];
        int lane = tid & 31, wp = tid >> 5;
        #pragma unroll
        for (int o = 1; o < 32; o <<= 1) {
            float ta = __shfl_up_sync(0xffffffffu, a, o);
            float tc = __shfl_up_sync(0xffffffffu, c, o);
            if (lane >= o) { a += ta; c += tc; }
        }
        if (lane == 31) { wsum[wp] = a; wsum[8 + wp] = c; }
        __syncthreads();
        if (wp == 0 && lane < 8) {
            float v1 = wsum[lane], v2 = wsum[8 + lane];
            #pragma unroll
            for (int o = 1; o < 8; o <<= 1) {
                float t1 = __shfl_up_sync(0xffu, v1, o);
                float t2 = __shfl_up_sync(0xffu, v2, o);
                if (lane >= o) { v1 += t1; v2 += t2; }
            }
            wsum[lane] = v1; wsum[8 + lane] = v2;
        }
        __syncthreads();
        float o1 = off[((size_t)bg*TNC + ch_)*2];
        float o2 = off[((size_t)bg*TNC + ch_)*2 + 1];
        if (wp > 0) { o1 += wsum[wp - 1]; o2 += wsum[8 + wp - 1]; }
        c1[tid] = a + o1;
        c2[tid] = c + o2;
    }
    __syncthreads();

    float pm = pm_[g];
    float pv = expf(plv_[g]);
    int lane8 = tid & 7;
    int trow = tid >> 3;
    float4 wg4 = *(const float4*)(w + g*MG + lane8*4);
    float4 bs4 = *(const float4*)(bias + g*MG + lane8*4);
    const float* xp = x + (size_t)b*LL*DD + g*MG + lane8*4;
    __half* op = xn + (size_t)b*LL*DD + g*MG + lane8*4;
    #pragma unroll
    for (int wv = 0; wv < TCH/32; wv++) {
        int t = wv*32 + trow;
        int tg = t0 + t;
        float cnt  = PRIORC + (float)MG * (float)(tg + 1);
        float mean = (PRIORC*pm + c1[t]) / cnt;
        float var  = (PRIORC*(pv + pm*pm) + c2[t]) / cnt - mean*mean;
        float inv  = rsqrtf(var + EPSF);
        float4 v = *(const float4*)(xp + (size_t)tg*DD);
        uint2 o;
        o.x = packh2((v.x - mean)*inv*wg4.x + bs4.x, (v.y - mean)*inv*wg4.y + bs4.y);
        o.y = packh2((v.z - mean)*inv*wg4.z + bs4.z, (v.w - mean)*inv*wg4.w + bs4.w);
        *(uint2*)(op + (size_t)tg*DD) = o;
    }
}

// ---------------- MultiHeadEMA: chunked parallel scan (half input) ----------------
__global__ void ema2_kernel(const __half* __restrict__ xn,
                            const float* __restrict__ delta, const float* __restrict__ alpha,
                            const float* __restrict__ ebeta, const float* __restrict__ egamma,
                            const float* __restrict__ omega, float* __restrict__ out) {
    __shared__ float fin[EC][16][NE];
    __shared__ float ini[EC][16][NE];
    int blk = blockIdx.x;
    int b = blk >> 6;
    int d0 = (blk & 63) << 4;
    int tid = threadIdx.x;
    int ch = tid & 15, ck = tid >> 4;
    int d = d0 + ch;

    float q[NE], c[NE], s[NE];
    const float scale = 0.25f;
    #pragma unroll
    for (int n = 0; n < NE; n++) {
        float p = 1.f/(1.f+expf(-delta[d*NE+n]));
        float a = 1.f/(1.f+expf(-alpha[d*NE+n]));
        q[n] = 1.f - p*a;
        c[n] = p * ebeta[d*NE+n] * egamma[d*NE+n] * scale;
        s[n] = 0.f;
    }
    const __half* xp = xn + ((size_t)b*LL + (size_t)ck*ECL)*DD + d;

    for (int t = 0; t < ECL; t++) {
        float xv = __half2float(xp[(size_t)t*DD]);
        #pragma unroll
        for (int n = 0; n < NE; n++) s[n] = q[n]*s[n] + xv;
    }
    #pragma unroll
    for (int n = 0; n < NE; n++) fin[ck][ch][n] = s[n];
    __syncthreads();

    {
        int ch2 = tid >> 4, n2 = tid & 15;
        int d2 = d0 + ch2;
        float p2 = 1.f/(1.f+expf(-delta[d2*NE+n2]));
        float a2 = 1.f/(1.f+expf(-alpha[d2*NE+n2]));
        float qq = 1.f - p2*a2;
        float q128 = __powf(qq, (float)ECL);
        float st = 0.f;
        #pragma unroll
        for (int k2 = 0; k2 < EC; k2++) {
            ini[k2][ch2][n2] = st;
            st = q128*st + fin[k2][ch2][n2];
        }
    }
    __syncthreads();

    #pragma unroll
    for (int n = 0; n < NE; n++) s[n] = ini[ck][ch][n];
    float om = omega[d];
    float* op = out + ((size_t)b*LL + (size_t)ck*ECL)*DD + d;
    for (int t = 0; t < ECL; t++) {
        float xv = __half2float(xp[(size_t)t*DD]);
        float acc = 0.f;
        #pragma unroll
        for (int n = 0; n < NE; n++) { s[n] = q[n]*s[n] + xv; acc += c[n]*s[n]; }
        op[(size_t)t*DD] = acc + om*xv;
    }
}

// ---------------- RMS norm: fp32 in -> half out ----------------
__global__ void rms_kernel(const float* __restrict__ mx, const float* __restrict__ w,
                           __half* __restrict__ outh) {
    int row = blockIdx.x;
    int tid = threadIdx.x;
    const float* p = mx + (size_t)row*DD;
    float v[4];
    float ss = 0.f;
    #pragma unroll
    for (int i = 0; i < 4; i++) { v[i] = p[tid + 256*i]; ss += v[i]*v[i]; }
    __shared__ float red[256];
    red[tid] = ss; __syncthreads();
    #pragma unroll
    for (int o = 128; o; o >>= 1) { if (tid < o) red[tid] += red[tid+o]; __syncthreads(); }
    float inv = rsqrtf(red[0]/(float)DD + EPSF);
    __half* oh = outh + (size_t)row*DD;
    #pragma unroll
    for (int i = 0; i < 4; i++) { int dc = tid + 256*i; oh[dc] = __float2half(v[i]*inv*w[dc]); }
}

// ============ fp16 tensor-core GEMM (NT), cp.async 2-stage ============
// C[m,n] = sum_k A[m,k]*B[n,k] (+bias, act).  All operand data __half.
// CAUSAL: skip blocks above diagonal. KLIM: K clamped to rowBase+128.
// OUT: 0 = float, 1 = half row-major, 2 = half transposed per batch of LL rows (v^T).
// act: 0 none, 1 silu, 3 *= silu(aux), 4 final gate.
template<int CAUSAL, int KLIM, int OUT>
__global__ void __launch_bounds__(256, 2)
hgemm(const __half* __restrict__ A, const __half* __restrict__ B,
      const float* __restrict__ bias, void* __restrict__ Cv,
      int M, int Nn, int K,
      long long sA, long long sB, long long sC, int act,
      const float* __restrict__ aux, const float* __restrict__ xres) {
    int rowBase = blockIdx.y * 128, colBase = blockIdx.x * 128;
    if (CAUSAL && colBase > rowBase) return;
    A += (long long)blockIdx.z * sA;
    B += (long long)blockIdx.z * sB;

    __shared__ unsigned sm[8192];   // 2 stages x (A 2048 + B 2048) uints = 32KB
    unsigned sbase = (unsigned)__cvta_generic_to_shared(sm);

    const int tid = threadIdx.x;
    const int lane = tid & 31, wid = tid >> 5;
    const int wm = (wid >> 2) * 64, wn = (wid & 3) * 32;
    const int g = lane >> 2, t = lane & 3;

    const int Kend = KLIM ? (rowBase + 128) : K;
    const int NIT = Kend >> 5;

    // staging: 512 chunks of 16B per matrix, 2 per thread
    unsigned dst[2];
    const __half* agp[2];
    const __half* bgp[2];
    #pragma unroll
    for (int i = 0; i < 2; i++) {
        int idx = tid + 256*i;
        int r = idx >> 2, c = idx & 3;
        unsigned csw = (unsigned)(c ^ ((r >> 1) & 3));
        dst[i] = (unsigned)(r*64 + csw*16);
        agp[i] = A + (long long)(rowBase + r)*K + c*8;
        bgp[i] = B + (long long)(colBase + r)*K + c*8;
    }

    auto issue = [&](int it) {
        unsigned stg = sbase + (unsigned)((it & 1) * 16384);
        long long ka = (long long)it * 32;
        #pragma unroll
        for (int i = 0; i < 2; i++) cpa16(stg + dst[i], agp[i] + ka);
        #pragma unroll
        for (int i = 0; i < 2; i++) cpa16(stg + 8192u + dst[i], bgp[i] + ka);
        cpcommit();
    };

    float acc[4][4][4];
    #pragma unroll
    for (int mi = 0; mi < 4; mi++)
        #pragma unroll
        for (int ni = 0; ni < 4; ni++)
            #pragma unroll
            for (int e = 0; e < 4; e++) acc[mi][ni][e] = 0.f;

    issue(0);

    for (int it = 0; it < NIT; it++) {
        if (it + 1 < NIT) { issue(it + 1); cpwait<1>(); }
        else              { cpwait<0>(); }
        __syncthreads();

        const unsigned* Ab = sm + (it & 1) * 4096;
        const unsigned* Bb = Ab + 2048;

        #pragma unroll
        for (int ks = 0; ks < 2; ks++) {
            unsigned af[4][4], bf[4][2];
            #pragma unroll
            for (int mi = 0; mi < 4; mi++) {
                int r0 = wm + mi*16 + g;
                int r1 = r0 + 8;
                int sw0 = ((r0 >> 1) & 3) << 2;
                int sw1 = ((r1 >> 1) & 3) << 2;
                int ca = ks*8 + t;
                af[mi][0] = Ab[r0*16 + (ca ^ sw0)];
                af[mi][1] = Ab[r1*16 + (ca ^ sw1)];
                af[mi][2] = Ab[r0*16 + ((ca + 4) ^ sw0)];
                af[mi][3] = Ab[r1*16 + ((ca + 4) ^ sw1)];
            }
            #pragma unroll
            for (int ni = 0; ni < 4; ni++) {
                int n0 = wn + ni*8 + g;
                int swb = ((n0 >> 1) & 3) << 2;
                int ca = ks*8 + t;
                bf[ni][0] = Bb[n0*16 + (ca ^ swb)];
                bf[ni][1] = Bb[n0*16 + ((ca + 4) ^ swb)];
            }
            #pragma unroll
            for (int mi = 0; mi < 4; mi++)
                #pragma unroll
                for (int ni = 0; ni < 4; ni++) {
                    asm volatile(
                        "mma.sync.aligned.m16n8k16.row.col.f32.f16.f16.f32 "
                        "{%0,%1,%2,%3},{%4,%5,%6,%7},{%8,%9},{%0,%1,%2,%3};"
                        : "+f"(acc[mi][ni][0]), "+f"(acc[mi][ni][1]),
                          "+f"(acc[mi][ni][2]), "+f"(acc[mi][ni][3])
                        : "r"(af[mi][0]), "r"(af[mi][1]), "r"(af[mi][2]), "r"(af[mi][3]),
                          "r"(bf[ni][0]), "r"(bf[ni][1]));
                }
        }
        __syncthreads();
    }

    // epilogue
    const float* auxb = aux ? aux + (long long)blockIdx.z * LL * NOUT : aux;
    float* Cf = (float*)Cv;
    __half* Ch = (__half*)Cv;
    if (OUT == 0) Cf += (long long)blockIdx.z * sC;
    if (OUT == 1) Ch += (long long)blockIdx.z * sC;

    #pragma unroll
    for (int mi = 0; mi < 4; mi++) {
        #pragma unroll
        for (int ni = 0; ni < 4; ni++) {
            int c = colBase + wn + ni*8 + 2*t;
            float b0 = 0.f, b1 = 0.f;
            if (bias) { b0 = bias[c]; b1 = bias[c+1]; }
            #pragma unroll
            for (int h = 0; h < 2; h++) {
                long long r = rowBase + wm + mi*16 + g + 8*h;
                float v0 = acc[mi][ni][2*h]   + b0;
                float v1 = acc[mi][ni][2*h+1] + b1;
                if (act == 1) { v0 = siluf_(v0); v1 = siluf_(v1); }
                else if (act == 3) {
                    v0 *= siluf_(auxb[r*NOUT + c]);
                    v1 *= siluf_(auxb[r*NOUT + c + 1]);
                } else if (act == 4) {
                    float u0  = sigmoidf_(auxb[r*NOUT + c]);
                    float u1  = sigmoidf_(auxb[r*NOUT + c + 1]);
                    float hx0 = auxb[r*NOUT + (DD+ZZ+HH) + c];
                    float hx1 = auxb[r*NOUT + (DD+ZZ+HH) + c + 1];
                    float x0  = xres[r*Nn + c];
                    float x1  = xres[r*Nn + c + 1];
                    v0 = x0 + u0*(siluf_(hx0 + v0) - x0);
                    v1 = x1 + u1*(siluf_(hx1 + v1) - x1);
                }
                if (OUT == 0) {
                    *(float2*)&Cf[r*Nn + c] = make_float2(v0, v1);
                } else if (OUT == 1) {
                    *(unsigned*)&Ch[r*Nn + c] = packh2(v0, v1);
                } else {
                    // v^T: [b][n][l]
                    long long b = r >> 11;
                    long long rl = r & (LL - 1);
                    Ch[(b*Nn + c)*LL + rl]     = __float2half(v0);
                    Ch[(b*Nn + c + 1)*LL + rl] = __float2half(v1);
                }
            }
        }
    }
}

// ---------------- q/k projection -> half ----------------
__global__ void prepqk_kernel(const float* __restrict__ base,
                              const float* __restrict__ qg, const float* __restrict__ qb,
                              __half* __restrict__ q, __half* __restrict__ k) {
    int gid = blockIdx.x*blockDim.x + threadIdx.x;
    if (gid >= BB*LL*ZZ) return;
    int zi  = gid & (ZZ-1);
    int row = gid >> 7;
    float v = base[(size_t)row*NOUT + DD + zi];
    v = siluf_(v);
    q[gid] = __float2half((v*qg[zi]    + qb[zi]) * 0.08838834764831845f);
    k[gid] = __float2half( v*qg[ZZ+zi] + qb[ZZ+zi]);
}

// ---------------- softmax: fp32 S in, half P out ----------------
__global__ void softmax_kernel(const float* __restrict__ S, const float* __restrict__ rel,
                               __half* __restrict__ P) {
    int i = blockIdx.x, b = blockIdx.y;
    int tid = threadIdx.x;
    const float* row = S + ((size_t)b*LL + i)*LL;
    __half* prow = P + ((size_t)b*LL + i)*LL;
    __shared__ float sh[LL];
    __shared__ float red[256];
    int len = i + 1;
    const float* rb = rel + (MAXPOSC - 1) - i;
    float mx = -1e30f;
    for (int j = tid; j < len; j += 256) {
        float v = row[j] + rb[j];
        sh[j] = v; mx = fmaxf(mx, v);
    }
    red[tid] = mx; __syncthreads();
    #pragma unroll
    for (int o = 128; o; o >>= 1) { if (tid < o) red[tid] = fmaxf(red[tid], red[tid+o]); __syncthreads(); }
    mx = red[0]; __syncthreads();
    float sum = 0.f;
    for (int j = tid; j < len; j += 256) { float e = __expf(sh[j]-mx); sh[j] = e; sum += e; }
    red[tid] = sum; __syncthreads();
    #pragma unroll
    for (int o = 128; o; o >>= 1) { if (tid < o) red[tid] += red[tid+o]; __syncthreads(); }
    float inv = 1.f / red[0];
    for (int j = tid; j < len; j += 256) prow[j] = __float2half(sh[j]*inv);
    int zend = ((i >> 7) + 1) << 7;
    for (int j = len + tid; j < zend; j += 256) prow[j] = __float2half(0.f);
}

// ---------------- host launch ----------------
extern "C" void kernel_launch(void* const* d_in, const int* in_sizes, int n_in,
                              void* d_out, int out_size) {
    const float* x      = (const float*)d_in[0];
    const float* pm     = (const float*)d_in[1];
    const float* plv    = (const float*)d_in[2];
    const float* tnw    = (const float*)d_in[3];
    const float* tnb    = (const float*)d_in[4];
    const float* delta  = (const float*)d_in[5];
    const float* alpha  = (const float*)d_in[6];
    const float* ebeta  = (const float*)d_in[7];
    const float* egamma = (const float*)d_in[8];
    const float* omega  = (const float*)d_in[9];
    const float* rmsw   = (const float*)d_in[10];
    const float* Wv     = (const float*)d_in[11];
    const float* bv     = (const float*)d_in[12];
    const float* Wmx    = (const float*)d_in[13];
    const float* bmx    = (const float*)d_in[14];
    const float* Wh     = (const float*)d_in[15];
    const float* qg     = (const float*)d_in[16];
    const float* qb     = (const float*)d_in[17];
    const float* rel    = (const float*)d_in[18];

    __half *xnh, *vT, *mxh, *qh, *kh, *Ph, *hatth, *wvh, *wmxh, *whh;
    float *mx, *base, *S, *ts1, *ts2, *ct, *off;
    cudaGetSymbolAddress((void**)&xnh,   g_xnh);
    cudaGetSymbolAddress((void**)&vT,    g_vT);
    cudaGetSymbolAddress((void**)&mx,    g_mx);
    cudaGetSymbolAddress((void**)&mxh,   g_mxh);
    cudaGetSymbolAddress((void**)&base,  g_base);
    cudaGetSymbolAddress((void**)&qh,    g_qh);
    cudaGetSymbolAddress((void**)&kh,    g_kh);
    cudaGetSymbolAddress((void**)&S,     g_S);
    cudaGetSymbolAddress((void**)&Ph,    g_Ph);
    cudaGetSymbolAddress((void**)&hatth, g_hatth);
    cudaGetSymbolAddress((void**)&wvh,   g_Wvh);
    cudaGetSymbolAddress((void**)&wmxh,  g_Wmxh);
    cudaGetSymbolAddress((void**)&whh,   g_Whh);
    cudaGetSymbolAddress((void**)&ts1,   g_ts1);
    cudaGetSymbolAddress((void**)&ts2,   g_ts2);
    cudaGetSymbolAddress((void**)&ct,    g_ct);
    cudaGetSymbolAddress((void**)&off,   g_off);

    const int Mrows = BB*LL;

    // 0) fp16 weight copies
    roundh_kernel<<<(HH*DD/4 + 255)/256, 256>>>(Wv,  wvh,  HH*DD/4);
    roundh_kernel<<<(NOUT*DD/4 + 255)/256, 256>>>(Wmx, wmxh, NOUT*DD/4);
    roundh_kernel<<<(DD*HH/4 + 255)/256, 256>>>(Wh,  whh,  DD*HH/4);

    // 1) timestep norm -> xn (half)
    tn1_kernel<<<BB*GG*TNC, 256>>>(x, ts1, ts2, ct);
    tn2_kernel<<<1, 256>>>(ct, off);
    tn3_kernel<<<BB*GG*TNC, 256>>>(x, ts1, ts2, off, pm, plv, tnw, tnb, xnh);

    // 2) v^T = silu(xn @ Wv^T + bv), transposed half output
    hgemm<0,0,2><<<dim3(HH/128, Mrows/128, 1), 256>>>(
        xnh, wvh, bv, vT, Mrows, HH, DD, 0, 0, 0, 1, nullptr, nullptr);

    // 3) EMA (half in, fp32 out)
    ema2_kernel<<<(BB*DD)/16, 256>>>(xnh, delta, alpha, ebeta, egamma, omega, mx);

    // 4) RMS norm -> mx (half)
    rms_kernel<<<Mrows, 256>>>(mx, rmsw, mxh);

    // 5) base = mx @ Wmx^T + bmx (fp32 out)
    hgemm<0,0,0><<<dim3(NOUT/128, Mrows/128, 1), 256>>>(
        mxh, wmxh, bmx, base, Mrows, NOUT, DD, 0, 0, 0, 0, nullptr, nullptr);

    // 6) q, k (half)
    prepqk_kernel<<<(BB*LL*ZZ)/256, 256>>>(base, qg, qb, qh, kh);

    // 7) S = q @ k^T (fp32 out, lower-triangle blocks)
    hgemm<1,0,0><<<dim3(LL/128, LL/128, BB), 256>>>(
        qh, kh, nullptr, S, LL, LL, ZZ,
        (long long)LL*ZZ, (long long)LL*ZZ, (long long)LL*LL, 0, nullptr, nullptr);

    // 8) softmax -> P (half)
    softmax_kernel<<<dim3(LL, BB), 256>>>(S, rel, Ph);

    // 9) hatt = (P @ v) * silu(r)  (half out, K clamped)
    hgemm<0,1,1><<<dim3(HH/128, LL/128, BB), 256>>>(
        Ph, vT, nullptr, hatth, LL, HH, LL,
        (long long)LL*LL, (long long)LL*HH, (long long)LL*HH, 3, base + DD + ZZ, nullptr);

    // 10) out = x + u*(silu(hx + hatt @ Wh^T) - x)
    hgemm<0,0,0><<<dim3(DD/128, Mrows/128, 1), 256>>>(
        hatth, whh, nullptr, d_out, Mrows, DD, HH, 0, 0, 0, 4, base, x);
}

// round 15
// speedup vs baseline: 2.4661x; 1.0608x over previous
#include <cuda_runtime.h>
#include <cuda_fp16.h>
#include <math.h>

#define BB 8
#define LL 2048
#define DD 1024
#define ZZ 128
#define HH 2048
#define NE 16
#define GG 32
#define MG 32
#define NOUT 4224
#define MAXPOSC 2048
#define EPSF 1e-5f
#define PRIORC 2.0f
#define EC 16
#define ECL (LL/EC)
#define TCH 256
#define TNC (LL/TCH)

// ---------------- scratch ----------------
__device__ __half g_xnh [(size_t)BB*LL*DD];
__device__ __half g_vT  [(size_t)BB*LL*HH];   // [b][h][l]
__device__ float  g_mx  [(size_t)BB*LL*DD];
__device__ __half g_mxh [(size_t)BB*LL*DD];
__device__ float  g_base[(size_t)BB*LL*NOUT];
__device__ __half g_qh  [(size_t)BB*LL*ZZ];
__device__ __half g_kh  [(size_t)BB*LL*ZZ];
__device__ float  g_S   [(size_t)BB*LL*LL];
__device__ __half g_Ph  [(size_t)BB*LL*LL];
__device__ __half g_hatth[(size_t)BB*LL*HH];
__device__ __half g_Wvh [(size_t)HH*DD];
__device__ __half g_Wmxh[(size_t)NOUT*DD];
__device__ __half g_Whh [(size_t)DD*HH];
__device__ float  g_ts1[(size_t)BB*GG*LL];
__device__ float  g_ts2[(size_t)BB*GG*LL];
__device__ float  g_ct [(size_t)BB*GG*TNC*2];
__device__ float  g_off[(size_t)BB*GG*TNC*2];

// ---------------- fast transcendentals (no MUFU) ----------------
// e^x for x <= 0 (clamped), rel err ~4e-5
__device__ __forceinline__ float fexpn(float x) {
    float t = fmaxf(x, -87.f) * 1.4426950408889634f;
    float fi = rintf(t);
    float f = t - fi;
    float p = 9.6181291e-3f;
    p = fmaf(p, f, 5.5504109e-2f);
    p = fmaf(p, f, 2.4022651e-1f);
    p = fmaf(p, f, 6.9314718e-1f);
    p = fmaf(p, f, 1.0f);
    int ei = (int)fi;
    return p * __int_as_float((ei + 127) << 23);
}
// sigmoid via Newton reciprocal on d in (1,2]
__device__ __forceinline__ float fsig(float v) {
    float e = fexpn(-fabsf(v));
    float d = 1.f + e;
    float y = fmaf(-0.5f, d, 1.457f);
    y = y * (2.f - d*y);
    y = y * (2.f - d*y);
    return v >= 0.f ? y : e*y;
}
__device__ __forceinline__ float fsilu(float v) { return v * fsig(v); }

__device__ __forceinline__ void cpa16(unsigned d, const void* g) {
    asm volatile("cp.async.cg.shared.global [%0], [%1], 16;" :: "r"(d), "l"(g));
}
__device__ __forceinline__ void cpcommit() { asm volatile("cp.async.commit_group;"); }
template<int N> __device__ __forceinline__ void cpwait() {
    asm volatile("cp.async.wait_group %0;" :: "n"(N));
}
__device__ __forceinline__ unsigned packh2(float a, float b) {
    __half2 h = __floats2half2_rn(a, b);
    return *(unsigned*)&h;
}
__device__ __forceinline__ void ldsm4(unsigned& r0, unsigned& r1, unsigned& r2, unsigned& r3, unsigned addr) {
    asm volatile("ldmatrix.sync.aligned.m8n8.x4.shared.b16 {%0,%1,%2,%3}, [%4];"
        : "=r"(r0), "=r"(r1), "=r"(r2), "=r"(r3) : "r"(addr));
}
__device__ __forceinline__ void ldsm2(unsigned& r0, unsigned& r1, unsigned addr) {
    asm volatile("ldmatrix.sync.aligned.m8n8.x2.shared.b16 {%0,%1}, [%2];"
        : "=r"(r0), "=r"(r1) : "r"(addr));
}

// ---------------- fp32 -> fp16 copy ----------------
__global__ void roundh_kernel(const float* __restrict__ src, __half* __restrict__ dst, int n4) {
    int i = blockIdx.x*blockDim.x + threadIdx.x;
    if (i >= n4) return;
    float4 v = ((const float4*)src)[i];
    ((uint2*)dst)[i] = make_uint2(packh2(v.x, v.y), packh2(v.z, v.w));
}

// ---------------- TN phase 1 ----------------
__global__ void tn1_kernel(const float* __restrict__ x,
                           float* __restrict__ ts1, float* __restrict__ ts2,
                           float* __restrict__ ct) {
    int blk = blockIdx.x;
    int ch_ = blk & (TNC-1);
    int bg  = blk >> 3;
    int b = bg / GG, g = bg % GG;
    int tid = threadIdx.x;
    int lane8 = tid & 7;
    int trow = tid >> 3;
    __shared__ float sh1[TCH], sh2[TCH];

    const float* xp = x + (size_t)b*LL*DD + g*MG + lane8*4;
    int t0 = ch_*TCH;
    #pragma unroll
    for (int w = 0; w < TCH/32; w++) {
        int t = w*32 + trow;
        float4 v = *(const float4*)(xp + (size_t)(t0 + t)*DD);
        float s = v.x + v.y + v.z + v.w;
        float s2 = v.x*v.x + v.y*v.y + v.z*v.z + v.w*v.w;
        #pragma unroll
        for (int o = 4; o; o >>= 1) {
            s  += __shfl_xor_sync(0xffffffffu, s,  o);
            s2 += __shfl_xor_sync(0xffffffffu, s2, o);
        }
        if (lane8 == 0) { sh1[t] = s; sh2[t] = s2; }
    }
    __syncthreads();
    float* o1 = ts1 + (size_t)bg*LL + t0;
    float* o2 = ts2 + (size_t)bg*LL + t0;
    if (tid < TCH) { o1[tid] = sh1[tid]; o2[tid] = sh2[tid]; }
    __syncthreads();
    if (tid < 128) { sh1[tid] += sh1[tid+128]; sh2[tid] += sh2[tid+128]; }
    __syncthreads();
    if (tid < 64) { sh1[tid] += sh1[tid+64]; sh2[tid] += sh2[tid+64]; }
    __syncthreads();
    if (tid < 32) {
        float a = sh1[tid] + sh1[tid+32];
        float c = sh2[tid] + sh2[tid+32];
        #pragma unroll
        for (int o = 16; o; o >>= 1) {
            a += __shfl_xor_sync(0xffffffffu, a, o);
            c += __shfl_xor_sync(0xffffffffu, c, o);
        }
        if (tid == 0) {
            ct[((size_t)bg*TNC + ch_)*2]     = a;
            ct[((size_t)bg*TNC + ch_)*2 + 1] = c;
        }
    }
}

// ---------------- TN phase 2 ----------------
__global__ void tn2_kernel(const float* __restrict__ ct, float* __restrict__ off) {
    int bg = blockIdx.x*blockDim.x + threadIdx.x;
    if (bg >= BB*GG) return;
    float p1 = 0.f, p2 = 0.f;
    #pragma unroll
    for (int c = 0; c < TNC; c++) {
        off[((size_t)bg*TNC + c)*2]     = p1;
        off[((size_t)bg*TNC + c)*2 + 1] = p2;
        p1 += ct[((size_t)bg*TNC + c)*2];
        p2 += ct[((size_t)bg*TNC + c)*2 + 1];
    }
}

// ---------------- TN phase 3 ----------------
__global__ void tn3_kernel(const float* __restrict__ x,
                           const float* __restrict__ ts1, const float* __restrict__ ts2,
                           const float* __restrict__ off,
                           const float* __restrict__ pm_, const float* __restrict__ plv_,
                           const float* __restrict__ w, const float* __restrict__ bias,
                           __half* __restrict__ xn) {
    int blk = blockIdx.x;
    int ch_ = blk & (TNC-1);
    int bg  = blk >> 3;
    int b = bg / GG, g = bg % GG;
    int tid = threadIdx.x;
    __shared__ float c1[TCH], c2[TCH];
    __shared__ float wsum[16];

    int t0 = ch_*TCH;
    {
        float a = ts1[(size_t)bg*LL + t0 + tid];
        float c = ts2[(size_t)bg*LL + t0 + tid];
        int lane = tid & 31, wp = tid >> 5;
        #pragma unroll
        for (int o = 1; o < 32; o <<= 1) {
            float ta = __shfl_up_sync(0xffffffffu, a, o);
            float tc = __shfl_up_sync(0xffffffffu, c, o);
            if (lane >= o) { a += ta; c += tc; }
        }
        if (lane == 31) { wsum[wp] = a; wsum[8 + wp] = c; }
        __syncthreads();
        if (wp == 0 && lane < 8) {
            float v1 = wsum[lane], v2 = wsum[8 + lane];
            #pragma unroll
            for (int o = 1; o < 8; o <<= 1) {
                float t1 = __shfl_up_sync(0xffu, v1, o);
                float t2 = __shfl_up_sync(0xffu, v2, o);
                if (lane >= o) { v1 += t1; v2 += t2; }
            }
            wsum[lane] = v1; wsum[8 + lane] = v2;
        }
        __syncthreads();
        float o1 = off[((size_t)bg*TNC + ch_)*2];
        float o2 = off[((size_t)bg*TNC + ch_)*2 + 1];
        if (wp > 0) { o1 += wsum[wp - 1]; o2 += wsum[8 + wp - 1]; }
        c1[tid] = a + o1;
        c2[tid] = c + o2;
    }
    __syncthreads();

    float pm = pm_[g];
    float pv = expf(plv_[g]);
    int lane8 = tid & 7;
    int trow = tid >> 3;
    float4 wg4 = *(const float4*)(w + g*MG + lane8*4);
    float4 bs4 = *(const float4*)(bias + g*MG + lane8*4);
    const float* xp = x + (size_t)b*LL*DD + g*MG + lane8*4;
    __half* op = xn + (size_t)b*LL*DD + g*MG + lane8*4;
    #pragma unroll
    for (int wv = 0; wv < TCH/32; wv++) {
        int t = wv*32 + trow;
        int tg = t0 + t;
        float cnt  = PRIORC + (float)MG * (float)(tg + 1);
        float mean = (PRIORC*pm + c1[t]) / cnt;
        float var  = (PRIORC*(pv + pm*pm) + c2[t]) / cnt - mean*mean;
        float inv  = rsqrtf(var + EPSF);
        float4 v = *(const float4*)(xp + (size_t)tg*DD);
        uint2 o;
        o.x = packh2((v.x - mean)*inv*wg4.x + bs4.x, (v.y - mean)*inv*wg4.y + bs4.y);
        o.y = packh2((v.z - mean)*inv*wg4.z + bs4.z, (v.w - mean)*inv*wg4.w + bs4.w);
        *(uint2*)(op + (size_t)tg*DD) = o;
    }
}

// ---------------- MultiHeadEMA ----------------
__global__ void ema2_kernel(const __half* __restrict__ xn,
                            const float* __restrict__ delta, const float* __restrict__ alpha,
                            const float* __restrict__ ebeta, const float* __restrict__ egamma,
                            const float* __restrict__ omega, float* __restrict__ out) {
    __shared__ float fin[EC][16][NE];
    __shared__ float ini[EC][16][NE];
    int blk = blockIdx.x;
    int b = blk >> 6;
    int d0 = (blk & 63) << 4;
    int tid = threadIdx.x;
    int ch = tid & 15, ck = tid >> 4;
    int d = d0 + ch;

    float q[NE], c[NE], s[NE];
    const float scale = 0.25f;
    #pragma unroll
    for (int n = 0; n < NE; n++) {
        float p = 1.f/(1.f+expf(-delta[d*NE+n]));
        float a = 1.f/(1.f+expf(-alpha[d*NE+n]));
        q[n] = 1.f - p*a;
        c[n] = p * ebeta[d*NE+n] * egamma[d*NE+n] * scale;
        s[n] = 0.f;
    }
    const __half* xp = xn + ((size_t)b*LL + (size_t)ck*ECL)*DD + d;

    for (int t = 0; t < ECL; t++) {
        float xv = __half2float(xp[(size_t)t*DD]);
        #pragma unroll
        for (int n = 0; n < NE; n++) s[n] = q[n]*s[n] + xv;
    }
    #pragma unroll
    for (int n = 0; n < NE; n++) fin[ck][ch][n] = s[n];
    __syncthreads();

    {
        int ch2 = tid >> 4, n2 = tid & 15;
        int d2 = d0 + ch2;
        float p2 = 1.f/(1.f+expf(-delta[d2*NE+n2]));
        float a2 = 1.f/(1.f+expf(-alpha[d2*NE+n2]));
        float qq = 1.f - p2*a2;
        float q128 = __powf(qq, (float)ECL);
        float st = 0.f;
        #pragma unroll
        for (int k2 = 0; k2 < EC; k2++) {
            ini[k2][ch2][n2] = st;
            st = q128*st + fin[k2][ch2][n2];
        }
    }
    __syncthreads();

    #pragma unroll
    for (int n = 0; n < NE; n++) s[n] = ini[ck][ch][n];
    float om = omega[d];
    float* op = out + ((size_t)b*LL + (size_t)ck*ECL)*DD + d;
    for (int t = 0; t < ECL; t++) {
        float xv = __half2float(xp[(size_t)t*DD]);
        float acc = 0.f;
        #pragma unroll
        for (int n = 0; n < NE; n++) { s[n] = q[n]*s[n] + xv; acc += c[n]*s[n]; }
        op[(size_t)t*DD] = acc + om*xv;
    }
}

// ---------------- RMS norm ----------------
__global__ void rms_kernel(const float* __restrict__ mx, const float* __restrict__ w,
                           __half* __restrict__ outh) {
    int row = blockIdx.x;
    int tid = threadIdx.x;
    const float* p = mx + (size_t)row*DD;
    float v[4];
    float ss = 0.f;
    #pragma unroll
    for (int i = 0; i < 4; i++) { v[i] = p[tid + 256*i]; ss += v[i]*v[i]; }
    __shared__ float red[256];
    red[tid] = ss; __syncthreads();
    #pragma unroll
    for (int o = 128; o; o >>= 1) { if (tid < o) red[tid] += red[tid+o]; __syncthreads(); }
    float inv = rsqrtf(red[0]/(float)DD + EPSF);
    __half* oh = outh + (size_t)row*DD;
    #pragma unroll
    for (int i = 0; i < 4; i++) { int dc = tid + 256*i; oh[dc] = __float2half(v[i]*inv*w[dc]); }
}

// ============ fp16 tensor-core GEMM (NT), cp.async 2-stage, ldmatrix ============
template<int CAUSAL, int KLIM, int OUT>
__global__ void __launch_bounds__(256, 2)
hgemm(const __half* __restrict__ A, const __half* __restrict__ B,
      const float* __restrict__ bias, void* __restrict__ Cv,
      int M, int Nn, int K,
      long long sA, long long sB, long long sC, int act,
      const float* __restrict__ aux, const float* __restrict__ xres) {
    int rowBase = blockIdx.y * 128, colBase = blockIdx.x * 128;
    if (CAUSAL && colBase > rowBase) return;
    A += (long long)blockIdx.z * sA;
    B += (long long)blockIdx.z * sB;

    __shared__ unsigned sm[8192];   // 2 stages x (A 8KB + B 8KB)
    unsigned sbase = (unsigned)__cvta_generic_to_shared(sm);

    const int tid = threadIdx.x;
    const int lane = tid & 31, wid = tid >> 5;
    const int wm = (wid >> 2) * 64, wn = (wid & 3) * 32;
    const int g = lane >> 2, t = lane & 3;

    const int Kend = KLIM ? (rowBase + 128) : K;
    const int NIT = Kend >> 5;

    // staging
    unsigned dst[2];
    const __half* agp[2];
    const __half* bgp[2];
    #pragma unroll
    for (int i = 0; i < 2; i++) {
        int idx = tid + 256*i;
        int r = idx >> 2, c = idx & 3;
        unsigned csw = (unsigned)(c ^ ((r >> 1) & 3));
        dst[i] = (unsigned)(r*64 + csw*16);
        agp[i] = A + (long long)(rowBase + r)*K + c*8;
        bgp[i] = B + (long long)(colBase + r)*K + c*8;
    }

    // ldmatrix per-lane offsets (bytes within a stage)
    unsigned offA[4][2], offB[4][2];
    {
        int lmrow = lane & 15, lmk = lane >> 4;
        #pragma unroll
        for (int mi = 0; mi < 4; mi++) {
            int row = wm + mi*16 + lmrow;
            unsigned base = (unsigned)(row*64);
            unsigned sw = (unsigned)((row >> 1) & 3);
            #pragma unroll
            for (int ks = 0; ks < 2; ks++)
                offA[mi][ks] = base + ((((unsigned)(ks*2) + lmk) ^ sw) << 4);
        }
        int lnb = lane & 7, lkb = (lane >> 3) & 1;
        #pragma unroll
        for (int ni = 0; ni < 4; ni++) {
            int row = wn + ni*8 + lnb;
            unsigned base = 8192u + (unsigned)(row*64);
            unsigned sw = (unsigned)((row >> 1) & 3);
            #pragma unroll
            for (int ks = 0; ks < 2; ks++)
                offB[ni][ks] = base + ((((unsigned)(ks*2) + lkb) ^ sw) << 4);
        }
    }

    auto issue = [&](int it) {
        unsigned stg = sbase + (unsigned)((it & 1) * 16384);
        long long ka = (long long)it * 32;
        #pragma unroll
        for (int i = 0; i < 2; i++) cpa16(stg + dst[i], agp[i] + ka);
        #pragma unroll
        for (int i = 0; i < 2; i++) cpa16(stg + 8192u + dst[i], bgp[i] + ka);
        cpcommit();
    };

    float acc[4][4][4];
    #pragma unroll
    for (int mi = 0; mi < 4; mi++)
        #pragma unroll
        for (int ni = 0; ni < 4; ni++)
            #pragma unroll
            for (int e = 0; e < 4; e++) acc[mi][ni][e] = 0.f;

    issue(0);

    for (int it = 0; it < NIT; it++) {
        if (it + 1 < NIT) { issue(it + 1); cpwait<1>(); }
        else              { cpwait<0>(); }
        __syncthreads();

        unsigned stg = sbase + (unsigned)((it & 1) * 16384);

        #pragma unroll
        for (int ks = 0; ks < 2; ks++) {
            unsigned af[4][4], bf[4][2];
            #pragma unroll
            for (int mi = 0; mi < 4; mi++)
                ldsm4(af[mi][0], af[mi][1], af[mi][2], af[mi][3], stg + offA[mi][ks]);
            #pragma unroll
            for (int ni = 0; ni < 4; ni++)
                ldsm2(bf[ni][0], bf[ni][1], stg + offB[ni][ks]);
            #pragma unroll
            for (int mi = 0; mi < 4; mi++)
                #pragma unroll
                for (int ni = 0; ni < 4; ni++) {
                    asm volatile(
                        "mma.sync.aligned.m16n8k16.row.col.f32.f16.f16.f32 "
                        "{%0,%1,%2,%3},{%4,%5,%6,%7},{%8,%9},{%0,%1,%2,%3};"
                        : "+f"(acc[mi][ni][0]), "+f"(acc[mi][ni][1]),
                          "+f"(acc[mi][ni][2]), "+f"(acc[mi][ni][3])
                        : "r"(af[mi][0]), "r"(af[mi][1]), "r"(af[mi][2]), "r"(af[mi][3]),
                          "r"(bf[ni][0]), "r"(bf[ni][1]));
                }
        }
        __syncthreads();
    }

    // epilogue
    const float* auxb = aux ? aux + (long long)blockIdx.z * LL * NOUT : aux;
    float* Cf = (float*)Cv;
    __half* Ch = (__half*)Cv;
    if (OUT == 0) Cf += (long long)blockIdx.z * sC;
    if (OUT == 1) Ch += (long long)blockIdx.z * sC;

    #pragma unroll
    for (int mi = 0; mi < 4; mi++) {
        #pragma unroll
        for (int ni = 0; ni < 4; ni++) {
            int c = colBase + wn + ni*8 + 2*t;
            float b0 = 0.f, b1 = 0.f;
            if (bias) { b0 = bias[c]; b1 = bias[c+1]; }
            #pragma unroll
            for (int h = 0; h < 2; h++) {
                long long r = rowBase + wm + mi*16 + g + 8*h;
                float v0 = acc[mi][ni][2*h]   + b0;
                float v1 = acc[mi][ni][2*h+1] + b1;
                if (act == 1) { v0 = fsilu(v0); v1 = fsilu(v1); }
                else if (act == 3) {
                    v0 *= fsilu(auxb[r*NOUT + c]);
                    v1 *= fsilu(auxb[r*NOUT + c + 1]);
                } else if (act == 4) {
                    float u0  = fsig(auxb[r*NOUT + c]);
                    float u1  = fsig(auxb[r*NOUT + c + 1]);
                    float hx0 = auxb[r*NOUT + (DD+ZZ+HH) + c];
                    float hx1 = auxb[r*NOUT + (DD+ZZ+HH) + c + 1];
                    float x0  = xres[r*Nn + c];
                    float x1  = xres[r*Nn + c + 1];
                    v0 = x0 + u0*(fsilu(hx0 + v0) - x0);
                    v1 = x1 + u1*(fsilu(hx1 + v1) - x1);
                }
                if (OUT == 0) {
                    *(float2*)&Cf[r*Nn + c] = make_float2(v0, v1);
                } else if (OUT == 1) {
                    *(unsigned*)&Ch[r*Nn + c] = packh2(v0, v1);
                } else {
                    long long b = r >> 11;
                    long long rl = r & (LL - 1);
                    Ch[(b*Nn + c)*LL + rl]     = __float2half(v0);
                    Ch[(b*Nn + c + 1)*LL + rl] = __float2half(v1);
                }
            }
        }
    }
}

// ---------------- q/k projection -> half ----------------
__global__ void prepqk_kernel(const float* __restrict__ base,
                              const float* __restrict__ qg, const float* __restrict__ qb,
                              __half* __restrict__ q, __half* __restrict__ k) {
    int gid = blockIdx.x*blockDim.x + threadIdx.x;
    if (gid >= BB*LL*ZZ) return;
    int zi  = gid & (ZZ-1);
    int row = gid >> 7;
    float v = base[(size_t)row*NOUT + DD + zi];
    v = fsilu(v);
    q[gid] = __float2half((v*qg[zi]    + qb[zi]) * 0.08838834764831845f);
    k[gid] = __float2half( v*qg[ZZ+zi] + qb[ZZ+zi]);
}

// ---------------- softmax: fp32 S in, half P out ----------------
__global__ void softmax_kernel(const float* __restrict__ S, const float* __restrict__ rel,
                               __half* __restrict__ P) {
    int i = blockIdx.x, b = blockIdx.y;
    int tid = threadIdx.x;
    const float* row = S + ((size_t)b*LL + i)*LL;
    __half* prow = P + ((size_t)b*LL + i)*LL;
    __shared__ float sh[LL];
    __shared__ float red[256];
    int len = i + 1;
    const float* rb = rel + (MAXPOSC - 1) - i;
    float mx = -1e30f;
    for (int j = tid; j < len; j += 256) {
        float v = row[j] + rb[j];
        sh[j] = v; mx = fmaxf(mx, v);
    }
    red[tid] = mx; __syncthreads();
    #pragma unroll
    for (int o = 128; o; o >>= 1) { if (tid < o) red[tid] = fmaxf(red[tid], red[tid+o]); __syncthreads(); }
    mx = red[0]; __syncthreads();
    float sum = 0.f;
    for (int j = tid; j < len; j += 256) { float e = fexpn(sh[j]-mx); sh[j] = e; sum += e; }
    red[tid] = sum; __syncthreads();
    #pragma unroll
    for (int o = 128; o; o >>= 1) { if (tid < o) red[tid] += red[tid+o]; __syncthreads(); }
    float inv = 1.f / red[0];
    for (int j = tid; j < len; j += 256) prow[j] = __float2half(sh[j]*inv);
    int zend = ((i >> 7) + 1) << 7;
    for (int j = len + tid; j < zend; j += 256) prow[j] = __float2half(0.f);
}

// ---------------- host launch ----------------
extern "C" void kernel_launch(void* const* d_in, const int* in_sizes, int n_in,
                              void* d_out, int out_size) {
    const float* x      = (const float*)d_in[0];
    const float* pm     = (const float*)d_in[1];
    const float* plv    = (const float*)d_in[2];
    const float* tnw    = (const float*)d_in[3];
    const float* tnb    = (const float*)d_in[4];
    const float* delta  = (const float*)d_in[5];
    const float* alpha  = (const float*)d_in[6];
    const float* ebeta  = (const float*)d_in[7];
    const float* egamma = (const float*)d_in[8];
    const float* omega  = (const float*)d_in[9];
    const float* rmsw   = (const float*)d_in[10];
    const float* Wv     = (const float*)d_in[11];
    const float* bv     = (const float*)d_in[12];
    const float* Wmx    = (const float*)d_in[13];
    const float* bmx    = (const float*)d_in[14];
    const float* Wh     = (const float*)d_in[15];
    const float* qg     = (const float*)d_in[16];
    const float* qb     = (const float*)d_in[17];
    const float* rel    = (const float*)d_in[18];

    __half *xnh, *vT, *mxh, *qh, *kh, *Ph, *hatth, *wvh, *wmxh, *whh;
    float *mx, *base, *S, *ts1, *ts2, *ct, *off;
    cudaGetSymbolAddress((void**)&xnh,   g_xnh);
    cudaGetSymbolAddress((void**)&vT,    g_vT);
    cudaGetSymbolAddress((void**)&mx,    g_mx);
    cudaGetSymbolAddress((void**)&mxh,   g_mxh);
    cudaGetSymbolAddress((void**)&base,  g_base);
    cudaGetSymbolAddress((void**)&qh,    g_qh);
    cudaGetSymbolAddress((void**)&kh,    g_kh);
    cudaGetSymbolAddress((void**)&S,     g_S);
    cudaGetSymbolAddress((void**)&Ph,    g_Ph);
    cudaGetSymbolAddress((void**)&hatth, g_hatth);
    cudaGetSymbolAddress((void**)&wvh,   g_Wvh);
    cudaGetSymbolAddress((void**)&wmxh,  g_Wmxh);
    cudaGetSymbolAddress((void**)&whh,   g_Whh);
    cudaGetSymbolAddress((void**)&ts1,   g_ts1);
    cudaGetSymbolAddress((void**)&ts2,   g_ts2);
    cudaGetSymbolAddress((void**)&ct,    g_ct);
    cudaGetSymbolAddress((void**)&off,   g_off);

    const int Mrows = BB*LL;

    // 0) fp16 weight copies
    roundh_kernel<<<(HH*DD/4 + 255)/256, 256>>>(Wv,  wvh,  HH*DD/4);
    roundh_kernel<<<(NOUT*DD/4 + 255)/256, 256>>>(Wmx, wmxh, NOUT*DD/4);
    roundh_kernel<<<(DD*HH/4 + 255)/256, 256>>>(Wh,  whh,  DD*HH/4);

    // 1) timestep norm -> xn (half)
    tn1_kernel<<<BB*GG*TNC, 256>>>(x, ts1, ts2, ct);
    tn2_kernel<<<1, 256>>>(ct, off);
    tn3_kernel<<<BB*GG*TNC, 256>>>(x, ts1, ts2, off, pm, plv, tnw, tnb, xnh);

    // 2) v^T = silu(xn @ Wv^T + bv), transposed half output
    hgemm<0,0,2><<<dim3(HH/128, Mrows/128, 1), 256>>>(
        xnh, wvh, bv, vT, Mrows, HH, DD, 0, 0, 0, 1, nullptr, nullptr);

    // 3) EMA
    ema2_kernel<<<(BB*DD)/16, 256>>>(xnh, delta, alpha, ebeta, egamma, omega, mx);

    // 4) RMS norm -> mx (half)
    rms_kernel<<<Mrows, 256>>>(mx, rmsw, mxh);

    // 5) base = mx @ Wmx^T + bmx (fp32 out)
    hgemm<0,0,0><<<dim3(NOUT/128, Mrows/128, 1), 256>>>(
        mxh, wmxh, bmx, base, Mrows, NOUT, DD, 0, 0, 0, 0, nullptr, nullptr);

    // 6) q, k (half)
    prepqk_kernel<<<(BB*LL*ZZ)/256, 256>>>(base, qg, qb, qh, kh);

    // 7) S = q @ k^T (fp32 out, lower-triangle blocks)
    hgemm<1,0,0><<<dim3(LL/128, LL/128, BB), 256>>>(
        qh, kh, nullptr, S, LL, LL, ZZ,
        (long long)LL*ZZ, (long long)LL*ZZ, (long long)LL*LL, 0, nullptr, nullptr);

    // 8) softmax -> P (half)
    softmax_kernel<<<dim3(LL, BB), 256>>>(S, rel, Ph);

    // 9) hatt = (P @ v) * silu(r)  (half out, K clamped)
    hgemm<0,1,1><<<dim3(HH/128, LL/128, BB), 256>>>(
        Ph, vT, nullptr, hatth, LL, HH, LL,
        (long long)LL*LL, (long long)LL*HH, (long long)LL*HH, 3, base + DD + ZZ, nullptr);

    // 10) out = x + u*(silu(hx + hatt @ Wh^T) - x)
    hgemm<0,0,0><<<dim3(DD/128, Mrows/128, 1), 256>>>(
        hatth, whh, nullptr, d_out, Mrows, DD, HH, 0, 0, 0, 4, base, x);
}